// round 8
// baseline (speedup 1.0000x reference)
#include <cuda_runtime.h>
#include <math.h>

#define BB 64
#define SS 512
#define DD 1024
#define HH 1024
#define HH2 512
#define G3 1536
#define GINK 2080
#define SPKD 16
#define NBLK 148
#define NTHR 256

typedef unsigned long long ull;
union F2U { ull u; float2 f; };

#define FMA2(d, a, b) \
    asm("fma.rn.f32x2 %0, %1, %2, %0;" : "+l"(d) : "l"(a), "l"(b))

__device__ __forceinline__ ull dup2(float a) {
    ull d;
    asm("mov.b64 %0, {%1, %1};" : "=l"(d) : "f"(a));
    return d;
}

// K-split counts
#define KS_GATE 8     // seq gate GEMM: K=1024 (prev only), chunk 128
#define KS_GRU  11    // chunk 48 (3 tiles), last chunk 32
#define KS_EMO  32    // chunk 32 (2 tiles)

// ---------------- scratch (device globals; no allocation allowed) ----------------
static __device__ float g_xproj[(size_t)2 * SS * BB * G3];    // [dir][t][b][1536]
static __device__ float g_mem[(size_t)SS * BB * HH];           // [t][b][1024]
static __device__ float g_gcur[(size_t)SS * BB * 4096];        // precomputed cur/spk/pos/bias part
static __device__ float g_ghp[(size_t)KS_GRU * 2 * BB * G3];   // GRU gemm partials
static __device__ float g_gpre[(size_t)KS_GATE * BB * 4096];   // gate gemm partials (prev part)
static __device__ float g_gated[(size_t)BB * HH];
static __device__ float g_h1p[(size_t)KS_EMO * BB * HH];       // emo gemm1 partials
static __device__ float g_hln[(size_t)BB * HH];
static __device__ float g_o2p[(size_t)KS_EMO * BB * HH];       // emo gemm2 partials
static __device__ unsigned int g_cnt;    // zero-init
static __device__ unsigned int g_sense;  // zero-init

// self-resetting sense-reversal grid barrier (all NBLK blocks co-resident)
__device__ __forceinline__ void gsync(unsigned int& ls) {
    __syncthreads();
    if (threadIdx.x == 0) {
        unsigned int ns = ls ^ 1u;
        ls = ns;
        __threadfence();
        if (atomicAdd(&g_cnt, 1u) == NBLK - 1u) {
            g_cnt = 0u;
            __threadfence();
            *(volatile unsigned int*)&g_sense = ns;
        } else {
            while (*(volatile unsigned int*)&g_sense != ns) __nanosleep(20);
        }
        __threadfence();
    }
    __syncthreads();
}

__device__ __forceinline__ float sigm(float x) { return 1.f / (1.f + expf(-x)); }

// ---- M=64 x N=256 microkernel: 8m x 4 n-pairs per thread, broadcast-A ----
__device__ __forceinline__ void mk64(ull (&acc)[8][4],
                                     const float (*As)[68],
                                     const float (*Ws)[260],
                                     int tx, int ty) {
#pragma unroll
    for (int kk = 0; kk < 16; kk++) {
        float4 alo = *(const float4*)&As[kk][ty * 8];
        float4 ahi = *(const float4*)&As[kk][ty * 8 + 4];
        ull a2[8];
        a2[0] = dup2(alo.x); a2[1] = dup2(alo.y);
        a2[2] = dup2(alo.z); a2[3] = dup2(alo.w);
        a2[4] = dup2(ahi.x); a2[5] = dup2(ahi.y);
        a2[6] = dup2(ahi.z); a2[7] = dup2(ahi.w);
        ull b2[4];
#pragma unroll
        for (int jp = 0; jp < 4; jp++)
            b2[jp] = *(const ull*)&Ws[kk][2 * tx + 64 * jp];
#pragma unroll
        for (int i = 0; i < 8; i++)
#pragma unroll
            for (int jp = 0; jp < 4; jp++)
                FMA2(acc[i][jp], a2[i], b2[jp]);
    }
}

// ---------------- big GEMM: x_proj = x @ Wih.T + bih (both dirs) ----------------
__global__ __launch_bounds__(256) void xproj_kernel(
    const float* __restrict__ uf,
    const float* __restrict__ Wf_, const float* __restrict__ bf_,
    const float* __restrict__ Wb_, const float* __restrict__ bb_)
{
    __shared__ __align__(16) float As[16][132];
    __shared__ __align__(16) float Ws[16][132];
    const int tid = threadIdx.x;
    const int tx = tid & 15, ty = tid >> 4;
    const int Mbase = blockIdx.x * 128;
    const int Nbase = blockIdx.y * 128;
    const int dir = blockIdx.z;
    const float* W = dir ? Wb_ : Wf_;
    const float* bias = dir ? bb_ : bf_;

    const float* ap[8];
    const float* wp[8];
#pragma unroll
    for (int p = 0; p < 8; p++) {
        int i = tid + p * 256;
        int m = i >> 4, k = i & 15;
        int mg = Mbase + m;
        int tt = mg >> 6, b = mg & 63;
        int srow = dir ? (SS - 1 - tt) : tt;
        ap[p] = uf + ((size_t)b * SS + srow) * DD + k;
        wp[p] = W + (size_t)(Nbase + m) * DD + k;
    }

    ull acc[8][4];
#pragma unroll
    for (int i = 0; i < 8; i++)
#pragma unroll
        for (int j = 0; j < 4; j++) acc[i][j] = 0ull;

    float va[8], vw[8];
#pragma unroll
    for (int p = 0; p < 8; p++) { va[p] = ap[p][0]; vw[p] = wp[p][0]; }

    for (int kt = 0; kt < DD; kt += 16) {
        __syncthreads();
#pragma unroll
        for (int p = 0; p < 8; p++) {
            int i = tid + p * 256;
            As[i & 15][i >> 4] = va[p];
            Ws[i & 15][i >> 4] = vw[p];
        }
        __syncthreads();
        if (kt + 16 < DD) {
#pragma unroll
            for (int p = 0; p < 8; p++) {
                va[p] = ap[p][kt + 16];
                vw[p] = wp[p][kt + 16];
            }
        }
#pragma unroll
        for (int kk = 0; kk < 16; kk++) {
            float4 alo = *(const float4*)&As[kk][ty * 8];
            float4 ahi = *(const float4*)&As[kk][ty * 8 + 4];
            ull a2[8];
            a2[0] = dup2(alo.x); a2[1] = dup2(alo.y);
            a2[2] = dup2(alo.z); a2[3] = dup2(alo.w);
            a2[4] = dup2(ahi.x); a2[5] = dup2(ahi.y);
            a2[6] = dup2(ahi.z); a2[7] = dup2(ahi.w);
            ull b2[4];
#pragma unroll
            for (int jp = 0; jp < 4; jp++)
                b2[jp] = *(const ull*)&Ws[kk][2 * tx + 32 * jp];
#pragma unroll
            for (int i = 0; i < 8; i++)
#pragma unroll
                for (int jp = 0; jp < 4; jp++)
                    FMA2(acc[i][jp], a2[i], b2[jp]);
        }
    }

#pragma unroll
    for (int i = 0; i < 8; i++) {
        int mg = Mbase + ty * 8 + i;
        size_t rowb = ((size_t)dir * SS * BB + mg) * G3;
#pragma unroll
        for (int jp = 0; jp < 4; jp++) {
            int col = Nbase + 2 * tx + 32 * jp;
            F2U u; u.u = acc[i][jp];
            u.f.x += bias[col];
            u.f.y += bias[col + 1];
            *(float2*)&g_xproj[rowb + col] = u.f;
        }
    }
}

// ---------------- big GEMM: g_gcur = [cur,spk,pos] part of all gate projections + bias ----------------
// M = 512*64 (t,b), N = 4096 (4 gates x 1024), K = 1056 (1024 mem + 16 spk + 16 pos)
__global__ __launch_bounds__(256) void gcur_kernel(
    const float* __restrict__ spk, const float* __restrict__ pos,
    const float* __restrict__ Wf, const float* __restrict__ bf,
    const float* __restrict__ Wi, const float* __restrict__ bi,
    const float* __restrict__ Wo, const float* __restrict__ bo,
    const float* __restrict__ Wc, const float* __restrict__ bc)
{
    __shared__ __align__(16) float As[16][132];
    __shared__ __align__(16) float Ws[16][132];
    const int tid = threadIdx.x;
    const int tx = tid & 15, ty = tid >> 4;
    const int Mbase = blockIdx.x * 128;
    const int Nbase = blockIdx.y * 128;
    const int gate = Nbase >> 10;
    const float* W = (gate == 0) ? Wf : (gate == 1) ? Wi : (gate == 2) ? Wo : Wc;
    const float* bias = (gate == 0) ? bf : (gate == 1) ? bi : (gate == 2) ? bo : bc;
    const int wrow = Nbase & 1023;
    const int KTOT = 1056;

    ull acc[8][4];
#pragma unroll
    for (int i = 0; i < 8; i++)
#pragma unroll
        for (int j = 0; j < 4; j++) acc[i][j] = 0ull;

    float va[8], vw[8];
#pragma unroll
    for (int p = 0; p < 8; p++) {
        int i = tid + p * 256;
        int m = i >> 4, kg = i & 15;
        int mg = Mbase + m, t = mg >> 6, b = mg & 63;
        va[p] = g_mem[((size_t)t * BB + b) * HH + kg];     // kg < 16 < 1024
        vw[p] = W[(size_t)(wrow + m) * GINK + kg];
    }

    for (int kt = 0; kt < KTOT; kt += 16) {
        __syncthreads();
#pragma unroll
        for (int p = 0; p < 8; p++) {
            int i = tid + p * 256;
            As[i & 15][i >> 4] = va[p];
            Ws[i & 15][i >> 4] = vw[p];
        }
        __syncthreads();
        if (kt + 16 < KTOT) {
#pragma unroll
            for (int p = 0; p < 8; p++) {
                int i = tid + p * 256;
                int m = i >> 4, kg = kt + 16 + (i & 15);
                int mg = Mbase + m, t = mg >> 6, b = mg & 63;
                float v, wv;
                if (kg < 1024) {
                    v = g_mem[((size_t)t * BB + b) * HH + kg];
                    wv = W[(size_t)(wrow + m) * GINK + kg];
                } else if (kg < 1040) {
                    v = spk[((size_t)b * SS + t) * SPKD + (kg - 1024)];
                    wv = W[(size_t)(wrow + m) * GINK + 2048 + (kg - 1024)];
                } else {
                    v = pos[((size_t)b * SS + t) * SPKD + (kg - 1040)];
                    wv = W[(size_t)(wrow + m) * GINK + 2064 + (kg - 1040)];
                }
                va[p] = v;
                vw[p] = wv;
            }
        }
#pragma unroll
        for (int kk = 0; kk < 16; kk++) {
            float4 alo = *(const float4*)&As[kk][ty * 8];
            float4 ahi = *(const float4*)&As[kk][ty * 8 + 4];
            ull a2[8];
            a2[0] = dup2(alo.x); a2[1] = dup2(alo.y);
            a2[2] = dup2(alo.z); a2[3] = dup2(alo.w);
            a2[4] = dup2(ahi.x); a2[5] = dup2(ahi.y);
            a2[6] = dup2(ahi.z); a2[7] = dup2(ahi.w);
            ull b2[4];
#pragma unroll
            for (int jp = 0; jp < 4; jp++)
                b2[jp] = *(const ull*)&Ws[kk][2 * tx + 32 * jp];
#pragma unroll
            for (int i = 0; i < 8; i++)
#pragma unroll
                for (int jp = 0; jp < 4; jp++)
                    FMA2(acc[i][jp], a2[i], b2[jp]);
        }
    }

#pragma unroll
    for (int i = 0; i < 8; i++) {
        int mg = Mbase + ty * 8 + i;
#pragma unroll
        for (int jp = 0; jp < 4; jp++) {
            int off = 2 * tx + 32 * jp;
            F2U u; u.u = acc[i][jp];
            u.f.x += bias[wrow + off];
            u.f.y += bias[wrow + off + 1];
            *(float2*)&g_gcur[(size_t)mg * 4096 + Nbase + off] = u.f;
        }
    }
}

// ---------------- persistent GRU: 512 steps, 2 grid syncs per step ----------------
__global__ __launch_bounds__(NTHR, 1) void gru_persistent(
    const float* __restrict__ Whh_f, const float* __restrict__ Whh_b,
    const float* __restrict__ bhh_f, const float* __restrict__ bhh_b)
{
    __shared__ __align__(16) float As[16][68];
    __shared__ __align__(16) float Ws[16][260];
    const int tid = threadIdx.x;
    const int tx = tid & 31, ty = tid >> 5;
    const int bx = blockIdx.x;
    unsigned int ls = *(volatile unsigned int*)&g_sense;

    const int w = bx;
    const bool active = (w < 2 * 6 * KS_GRU);
    const int dir = w / (6 * KS_GRU);
    const int rem = w % (6 * KS_GRU);
    const int nt = rem / KS_GRU;
    const int ks = rem % KS_GRU;
    const float* W = dir ? Whh_b : Whh_f;
    const int Nbase = nt * 256;
    const int k0 = ks * 48;
    const int k1 = (k0 + 48 < HH2) ? (k0 + 48) : HH2;

    for (int t = 0; t < SS; t++) {
        if (active) {
            ull acc[8][4];
#pragma unroll
            for (int i = 0; i < 8; i++)
#pragma unroll
                for (int j = 0; j < 4; j++) acc[i][j] = 0ull;

            float va[4], vw[16];
#pragma unroll
            for (int p = 0; p < 4; p++) {
                int i = tid + p * 256;
                int m = i >> 4, kg = k0 + (i & 15);
                float v = 0.f;
                if (t > 0)
                    v = dir ? g_mem[((size_t)(SS - t) * BB + m) * HH + HH2 + kg]
                            : g_mem[((size_t)(t - 1) * BB + m) * HH + kg];
                va[p] = v;
            }
#pragma unroll
            for (int p = 0; p < 16; p++) {
                int i = tid + p * 256;
                int n = i >> 4, kg = k0 + (i & 15);
                vw[p] = W[(size_t)(Nbase + n) * HH2 + kg];
            }

            for (int kt = k0; kt < k1; kt += 16) {
                __syncthreads();
#pragma unroll
                for (int p = 0; p < 4; p++) {
                    int i = tid + p * 256;
                    As[i & 15][i >> 4] = va[p];
                }
#pragma unroll
                for (int p = 0; p < 16; p++) {
                    int i = tid + p * 256;
                    Ws[i & 15][i >> 4] = vw[p];
                }
                __syncthreads();
                if (kt + 16 < k1) {
#pragma unroll
                    for (int p = 0; p < 4; p++) {
                        int i = tid + p * 256;
                        int m = i >> 4, kg = kt + 16 + (i & 15);
                        float v = 0.f;
                        if (t > 0)
                            v = dir ? g_mem[((size_t)(SS - t) * BB + m) * HH + HH2 + kg]
                                    : g_mem[((size_t)(t - 1) * BB + m) * HH + kg];
                        va[p] = v;
                    }
#pragma unroll
                    for (int p = 0; p < 16; p++) {
                        int i = tid + p * 256;
                        int n = i >> 4, kg = kt + 16 + (i & 15);
                        vw[p] = W[(size_t)(Nbase + n) * HH2 + kg];
                    }
                }
                mk64(acc, As, Ws, tx, ty);
            }
#pragma unroll
            for (int i2 = 0; i2 < 8; i2++) {
                int m = ty * 8 + i2;
                size_t rowb = (((size_t)ks * 2 + dir) * BB + m) * G3;
#pragma unroll
                for (int jp = 0; jp < 4; jp++) {
                    int col = Nbase + 2 * tx + 64 * jp;
                    F2U u; u.u = acc[i2][jp];
                    *(float2*)&g_ghp[rowb + col] = u.f;
                }
            }
        }
        gsync(ls);

        for (int e = bx * NTHR + tid; e < 2 * BB * HH2; e += NBLK * NTHR) {
            int d2 = e >> 15;
            int b = (e >> 9) & 63;
            int i = e & 511;
            const float* bhh = d2 ? bhh_b : bhh_f;
            float hr = bhh[i], hz = bhh[HH2 + i], hn = bhh[2 * HH2 + i];
#pragma unroll
            for (int q = 0; q < KS_GRU; q++) {
                size_t base = (((size_t)q * 2 + d2) * BB + b) * G3;
                hr += g_ghp[base + i];
                hz += g_ghp[base + HH2 + i];
                hn += g_ghp[base + 2 * HH2 + i];
            }
            size_t xb = (((size_t)d2 * SS + t) * BB + b) * G3;
            float xr = g_xproj[xb + i], xz = g_xproj[xb + HH2 + i], xn = g_xproj[xb + 2 * HH2 + i];
            float hp = 0.f;
            if (t > 0)
                hp = d2 ? g_mem[((size_t)(SS - t) * BB + b) * HH + HH2 + i]
                        : g_mem[((size_t)(t - 1) * BB + b) * HH + i];
            float r = sigm(xr + hr);
            float z = sigm(xz + hz);
            float n2 = tanhf(xn + r * hn);
            float h = (1.f - z) * n2 + z * hp;
            if (d2 == 0) g_mem[((size_t)t * BB + b) * HH + i] = h;
            else         g_mem[((size_t)(SS - 1 - t) * BB + b) * HH + HH2 + i] = h;
        }
        gsync(ls);
    }
}

// ---------------- seq gate GEMM: A = prev (out[t-1]), N=4096 (16 tiles), K=1024 (8 chunks of 128) ----------------
__device__ __forceinline__ void gate_gemm(int t,
    const float* __restrict__ Wf, const float* __restrict__ Wi,
    const float* __restrict__ Wo, const float* __restrict__ Wc,
    const float* __restrict__ outp,
    float (*As)[68], float (*Ws)[260], int tx, int ty)
{
    const int tid = threadIdx.x;
    const int w = blockIdx.x;
    if (w >= 16 * KS_GATE) return;
    const int nt = w >> 3;
    const int ks = w & 7;
    const int Nbase = nt * 256;
    const int gate = Nbase >> 10;
    const float* W = (gate == 0) ? Wf : (gate == 1) ? Wi : (gate == 2) ? Wo : Wc;
    const int wrow = Nbase & 1023;
    const int k0 = ks * 128;
    const float* prow = outp + ((size_t)(t - 1)) * HH;   // + m*SS*HH

    ull acc[8][4];
#pragma unroll
    for (int i = 0; i < 8; i++)
#pragma unroll
        for (int j = 0; j < 4; j++) acc[i][j] = 0ull;

    float va[4], vw[16];
#pragma unroll
    for (int p = 0; p < 4; p++) {
        int i = tid + p * 256;
        int m = i >> 4, kg = k0 + (i & 15);
        va[p] = prow[(size_t)m * SS * HH + kg];
    }
#pragma unroll
    for (int p = 0; p < 16; p++) {
        int i = tid + p * 256;
        int n = i >> 4, kg = k0 + (i & 15);
        vw[p] = W[(size_t)(wrow + n) * GINK + 1024 + kg];
    }

    for (int kt = k0; kt < k0 + 128; kt += 16) {
        __syncthreads();
#pragma unroll
        for (int p = 0; p < 4; p++) {
            int i = tid + p * 256;
            As[i & 15][i >> 4] = va[p];
        }
#pragma unroll
        for (int p = 0; p < 16; p++) {
            int i = tid + p * 256;
            Ws[i & 15][i >> 4] = vw[p];
        }
        __syncthreads();
        if (kt + 16 < k0 + 128) {
#pragma unroll
            for (int p = 0; p < 4; p++) {
                int i = tid + p * 256;
                int m = i >> 4, kg = kt + 16 + (i & 15);
                va[p] = prow[(size_t)m * SS * HH + kg];
            }
#pragma unroll
            for (int p = 0; p < 16; p++) {
                int i = tid + p * 256;
                int n = i >> 4, kg = kt + 16 + (i & 15);
                vw[p] = W[(size_t)(wrow + n) * GINK + 1024 + kg];
            }
        }
        mk64(acc, (const float (*)[68])As, (const float (*)[260])Ws, tx, ty);
    }
#pragma unroll
    for (int i2 = 0; i2 < 8; i2++) {
        int m = ty * 8 + i2;
        size_t rowb = ((size_t)ks * BB + m) * 4096;
#pragma unroll
        for (int jp = 0; jp < 4; jp++) {
            int col = Nbase + 2 * tx + 64 * jp;
            F2U u; u.u = acc[i2][jp];
            *(float2*)&g_gpre[rowb + col] = u.f;
        }
    }
}

// ---------------- emo1 with fused gate-combine in A-prep ----------------
// N=1024 (4 tiles of 256), K=1024 (32 chunks of 32). Computes its own 64x32 'gated' chunk.
__device__ __forceinline__ void emo1_fused(int t, const float* __restrict__ W1e,
                                           const float* __restrict__ outp,
                                           float (*Gs)[68], float (*Ws)[260],
                                           int tx, int ty)
{
    const int tid = threadIdx.x;
    const int w = blockIdx.x;
    if (w >= 4 * KS_EMO) return;
    const int nt = w >> 5;
    const int ks = w & 31;
    const int Nbase = nt * 256;
    const int k0 = ks * 32;

    // ---- A-prep: compute gated[m][k0..k0+32) into Gs ----
#pragma unroll
    for (int p = 0; p < 8; p++) {
        int e = tid + p * 256;       // 0..2047
        int m = e >> 5, kl = e & 31;
        int i = k0 + kl;
        float gv;
        if (t == 0) {
            gv = g_mem[(size_t)m * HH + i];
        } else {
            const float* gc = &g_gcur[((size_t)t * BB + m) * 4096];
            float f = gc[i], ig = gc[1024 + i], o = gc[2048 + i], c = gc[3072 + i];
#pragma unroll
            for (int q = 0; q < KS_GATE; q++) {
                const float* gp = &g_gpre[((size_t)q * BB + m) * 4096];
                f += gp[i]; ig += gp[1024 + i]; o += gp[2048 + i]; c += gp[3072 + i];
            }
            float prev = outp[((size_t)m * SS + (t - 1)) * HH + i];
            f = sigm(f); ig = sigm(ig); o = sigm(o); c = tanhf(c);
            gv = o * tanhf(f * prev + ig * c);
            if (nt == 0) g_gated[(size_t)m * HH + i] = gv;
        }
        Gs[kl][m] = gv;
    }

    ull acc[8][4];
#pragma unroll
    for (int i = 0; i < 8; i++)
#pragma unroll
        for (int j = 0; j < 4; j++) acc[i][j] = 0ull;

    float vw[16];
#pragma unroll
    for (int p = 0; p < 16; p++) {
        int i = tid + p * 256;
        int n = i >> 4, kg = k0 + (i & 15);
        vw[p] = W1e[(size_t)(Nbase + n) * HH + kg];
    }

#pragma unroll
    for (int kt2 = 0; kt2 < 2; kt2++) {
        __syncthreads();
#pragma unroll
        for (int p = 0; p < 16; p++) {
            int i = tid + p * 256;
            Ws[i & 15][i >> 4] = vw[p];
        }
        __syncthreads();
        if (kt2 == 0) {
#pragma unroll
            for (int p = 0; p < 16; p++) {
                int i = tid + p * 256;
                int n = i >> 4, kg = k0 + 16 + (i & 15);
                vw[p] = W1e[(size_t)(Nbase + n) * HH + kg];
            }
        }
        mk64(acc, (const float (*)[68])(Gs + kt2 * 16), (const float (*)[260])Ws, tx, ty);
    }
#pragma unroll
    for (int i2 = 0; i2 < 8; i2++) {
        int m = ty * 8 + i2;
        size_t rowb = ((size_t)ks * BB + m) * HH;
#pragma unroll
        for (int jp = 0; jp < 4; jp++) {
            int col = Nbase + 2 * tx + 64 * jp;
            F2U u; u.u = acc[i2][jp];
            *(float2*)&g_h1p[rowb + col] = u.f;
        }
    }
}

// ---------------- emo2: A = hln, same shape as emo1 ----------------
__device__ __forceinline__ void emo2_gemm(const float* __restrict__ W2e,
                                          float (*As)[68], float (*Ws)[260],
                                          int tx, int ty)
{
    const int tid = threadIdx.x;
    const int w = blockIdx.x;
    if (w >= 4 * KS_EMO) return;
    const int nt = w >> 5;
    const int ks = w & 31;
    const int Nbase = nt * 256;
    const int k0 = ks * 32;

    ull acc[8][4];
#pragma unroll
    for (int i = 0; i < 8; i++)
#pragma unroll
        for (int j = 0; j < 4; j++) acc[i][j] = 0ull;

    float va[4], vw[16];
#pragma unroll
    for (int p = 0; p < 4; p++) {
        int i = tid + p * 256;
        int m = i >> 4, kg = k0 + (i & 15);
        va[p] = g_hln[(size_t)m * HH + kg];
    }
#pragma unroll
    for (int p = 0; p < 16; p++) {
        int i = tid + p * 256;
        int n = i >> 4, kg = k0 + (i & 15);
        vw[p] = W2e[(size_t)(Nbase + n) * HH + kg];
    }

#pragma unroll
    for (int kt2 = 0; kt2 < 2; kt2++) {
        __syncthreads();
#pragma unroll
        for (int p = 0; p < 4; p++) {
            int i = tid + p * 256;
            As[i & 15][i >> 4] = va[p];
        }
#pragma unroll
        for (int p = 0; p < 16; p++) {
            int i = tid + p * 256;
            Ws[i & 15][i >> 4] = vw[p];
        }
        __syncthreads();
        if (kt2 == 0) {
#pragma unroll
            for (int p = 0; p < 4; p++) {
                int i = tid + p * 256;
                int m = i >> 4, kg = k0 + 16 + (i & 15);
                va[p] = g_hln[(size_t)m * HH + kg];
            }
#pragma unroll
            for (int p = 0; p < 16; p++) {
                int i = tid + p * 256;
                int n = i >> 4, kg = k0 + 16 + (i & 15);
                vw[p] = W2e[(size_t)(Nbase + n) * HH + kg];
            }
        }
        mk64(acc, (const float (*)[68])As, (const float (*)[260])Ws, tx, ty);
    }
#pragma unroll
    for (int i2 = 0; i2 < 8; i2++) {
        int m = ty * 8 + i2;
        size_t rowb = ((size_t)ks * BB + m) * HH;
#pragma unroll
        for (int jp = 0; jp < 4; jp++) {
            int col = Nbase + 2 * tx + 64 * jp;
            F2U u; u.u = acc[i2][jp];
            *(float2*)&g_o2p[rowb + col] = u.f;
        }
    }
}

// ---------------- persistent gating kernel: 512 steps ----------------
__global__ __launch_bounds__(NTHR, 1) void gating_persistent(
    const float* __restrict__ Wfw, const float* __restrict__ Wiw,
    const float* __restrict__ Wow, const float* __restrict__ Wcw,
    const float* __restrict__ W1e, const float* __restrict__ b1e,
    const float* __restrict__ gln, const float* __restrict__ beta,
    const float* __restrict__ W2e, const float* __restrict__ b2e,
    float* __restrict__ out)
{
    __shared__ __align__(16) float As[16][68];
    __shared__ __align__(16) float Ws[16][260];
    __shared__ __align__(16) float Gs[32][68];
    __shared__ float sred[NTHR];
    __shared__ float stats[2];
    const int tid = threadIdx.x;
    const int tx = tid & 31, ty = tid >> 5;
    const int bx = blockIdx.x;
    unsigned int ls = *(volatile unsigned int*)&g_sense;

    for (int t = 0; t < SS; t++) {
        if (t > 0) {
            gate_gemm(t, Wfw, Wiw, Wow, Wcw, out, As, Ws, tx, ty);
            gsync(ls);
        }

        // emo GEMM1 with fused gate-combine
        emo1_fused(t, W1e, out, Gs, Ws, tx, ty);
        gsync(ls);

        // LayerNorm + ReLU (blocks 0..63)
        if (bx < BB) {
            const int b = bx;
            float v[4];
            float lsum = 0.f, lsq = 0.f;
#pragma unroll
            for (int j = 0; j < 4; j++) {
                int i = tid + j * NTHR;
                float x = b1e[i];
#pragma unroll
                for (int q = 0; q < KS_EMO; q++) x += g_h1p[((size_t)q * BB + b) * HH + i];
                v[j] = x; lsum += x; lsq += x * x;
            }
            sred[tid] = lsum; __syncthreads();
            for (int s2 = NTHR / 2; s2 > 0; s2 >>= 1) {
                if (tid < s2) sred[tid] += sred[tid + s2];
                __syncthreads();
            }
            if (tid == 0) stats[0] = sred[0] * (1.f / 1024.f);
            __syncthreads();
            sred[tid] = lsq; __syncthreads();
            for (int s2 = NTHR / 2; s2 > 0; s2 >>= 1) {
                if (tid < s2) sred[tid] += sred[tid + s2];
                __syncthreads();
            }
            if (tid == 0) stats[1] = sred[0] * (1.f / 1024.f);
            __syncthreads();
            float mu = stats[0];
            float var = stats[1] - mu * mu;
            float rs = rsqrtf(var + 1e-5f);
#pragma unroll
            for (int j = 0; j < 4; j++) {
                int i = tid + j * NTHR;
                float y = (v[j] - mu) * rs * gln[i] + beta[i];
                g_hln[(size_t)b * HH + i] = y > 0.f ? y : 0.f;
            }
        }
        gsync(ls);

        // emo GEMM2
        emo2_gemm(W2e, As, Ws, tx, ty);
        gsync(ls);

        // finalize out[t]
        for (int e = bx * NTHR + tid; e < BB * HH; e += NBLK * NTHR) {
            int b = e >> 10, i = e & 1023;
            float x = b2e[i];
#pragma unroll
            for (int q = 0; q < KS_EMO; q++) x += g_o2p[((size_t)q * BB + b) * HH + i];
            float res = (t == 0) ? g_mem[(size_t)b * HH + i] : g_gated[e];
            out[((size_t)b * SS + t) * HH + i] = x + res;
        }
        gsync(ls);
    }
}

// ---------------- host launcher: 4 graph nodes total ----------------
extern "C" void kernel_launch(void* const* d_in, const int* in_sizes, int n_in,
                              void* d_out, int out_size)
{
    (void)in_sizes; (void)n_in; (void)out_size;
    const float* uf    = (const float*)d_in[0];
    const float* spk   = (const float*)d_in[1];
    const float* pos   = (const float*)d_in[2];
    const float* Wih_f = (const float*)d_in[3];
    const float* Whh_f = (const float*)d_in[4];
    const float* bih_f = (const float*)d_in[5];
    const float* bhh_f = (const float*)d_in[6];
    const float* Wih_b = (const float*)d_in[7];
    const float* Whh_b = (const float*)d_in[8];
    const float* bih_b = (const float*)d_in[9];
    const float* bhh_b = (const float*)d_in[10];
    const float* Wfw   = (const float*)d_in[11];
    const float* bfb   = (const float*)d_in[12];
    const float* Wiw   = (const float*)d_in[13];
    const float* bib   = (const float*)d_in[14];
    const float* Wow   = (const float*)d_in[15];
    const float* bob   = (const float*)d_in[16];
    const float* Wcw   = (const float*)d_in[17];
    const float* bcb   = (const float*)d_in[18];
    const float* W1e   = (const float*)d_in[19];
    const float* b1e   = (const float*)d_in[20];
    const float* g_ln  = (const float*)d_in[21];
    const float* beta  = (const float*)d_in[22];
    const float* W2e   = (const float*)d_in[23];
    const float* b2e   = (const float*)d_in[24];
    float* out = (float*)d_out;

    // 1) x projections for both GRU directions
    xproj_kernel<<<dim3(256, 12, 2), 256>>>(uf, Wih_f, bih_f, Wih_b, bih_b);

    // 2) persistent bidirectional GRU recurrence
    gru_persistent<<<NBLK, NTHR>>>(Whh_f, Whh_b, bhh_f, bhh_b);

    // 3) precompute cur/spk/pos part of gate projections (parallel)
    gcur_kernel<<<dim3(256, 32), 256>>>(spk, pos, Wfw, bfb, Wiw, bib,
                                        Wow, bob, Wcw, bcb);

    // 4) persistent dialogue gating loop
    gating_persistent<<<NBLK, NTHR>>>(Wfw, Wiw, Wow, Wcw,
                                      W1e, b1e, g_ln, beta, W2e, b2e, out);
}

// round 9
// speedup vs baseline: 1.5190x; 1.5190x over previous
#include <cuda_runtime.h>
#include <math.h>

#define BB 64
#define SS 512
#define DD 1024
#define HH 1024
#define HH2 512
#define G3 1536
#define GINK 2080
#define SPKD 16
#define NBLK 148
#define NTHR 256

typedef unsigned long long ull;
union F2U { ull u; float2 f; };

#define FMA2(d, a, b) \
    asm("fma.rn.f32x2 %0, %1, %2, %0;" : "+l"(d) : "l"(a), "l"(b))

__device__ __forceinline__ ull dup2(float a) {
    ull d;
    asm("mov.b64 %0, {%1, %1};" : "=l"(d) : "f"(a));
    return d;
}

// K-split counts
#define KS_GATE 8     // seq gate GEMM: K=1024 (prev only), chunk 128
#define KS_GRU  11    // chunk 48 (3 tiles), last chunk 32
#define KS_EMO  32    // chunk 32 (2 tiles)

// ---------------- scratch (device globals; no allocation allowed) ----------------
static __device__ float g_xproj[(size_t)2 * SS * BB * G3];    // [dir][t][b][1536]
static __device__ float g_mem[(size_t)SS * BB * HH];           // [t][b][1024]
static __device__ float g_gcur[(size_t)SS * BB * 4096];        // precomputed cur/spk/pos/bias part
static __device__ float g_ghp[(size_t)KS_GRU * 2 * BB * G3];   // GRU gemm partials
static __device__ float g_gpre[(size_t)KS_GATE * BB * 4096];   // gate gemm partials (prev part)
static __device__ float g_gated[(size_t)BB * HH];
static __device__ float g_h1p[(size_t)KS_EMO * BB * HH];       // emo gemm1 partials
static __device__ float g_hln[(size_t)BB * HH];
static __device__ float g_o2p[(size_t)KS_EMO * BB * HH];       // emo gemm2 partials
static __device__ unsigned int g_cnt;    // zero-init
static __device__ unsigned int g_sense;  // zero-init

// self-resetting sense-reversal grid barrier (all NBLK blocks co-resident)
__device__ __forceinline__ void gsync(unsigned int& ls) {
    __syncthreads();
    if (threadIdx.x == 0) {
        unsigned int ns = ls ^ 1u;
        ls = ns;
        __threadfence();
        if (atomicAdd(&g_cnt, 1u) == NBLK - 1u) {
            g_cnt = 0u;
            __threadfence();
            *(volatile unsigned int*)&g_sense = ns;
        } else {
            while (*(volatile unsigned int*)&g_sense != ns) __nanosleep(20);
        }
        __threadfence();
    }
    __syncthreads();
}

__device__ __forceinline__ float sigm(float x) { return 1.f / (1.f + expf(-x)); }

// ---- M=64 x N=256 microkernel: 8m x 4 n-pairs per thread, broadcast-A ----
__device__ __forceinline__ void mk64(ull (&acc)[8][4],
                                     const float (*As)[68],
                                     const float (*Ws)[260],
                                     int tx, int ty) {
#pragma unroll
    for (int kk = 0; kk < 16; kk++) {
        float4 alo = *(const float4*)&As[kk][ty * 8];
        float4 ahi = *(const float4*)&As[kk][ty * 8 + 4];
        ull a2[8];
        a2[0] = dup2(alo.x); a2[1] = dup2(alo.y);
        a2[2] = dup2(alo.z); a2[3] = dup2(alo.w);
        a2[4] = dup2(ahi.x); a2[5] = dup2(ahi.y);
        a2[6] = dup2(ahi.z); a2[7] = dup2(ahi.w);
        ull b2[4];
#pragma unroll
        for (int jp = 0; jp < 4; jp++)
            b2[jp] = *(const ull*)&Ws[kk][2 * tx + 64 * jp];
#pragma unroll
        for (int i = 0; i < 8; i++)
#pragma unroll
            for (int jp = 0; jp < 4; jp++)
                FMA2(acc[i][jp], a2[i], b2[jp]);
    }
}

// ---------------- big GEMM: x_proj = x @ Wih.T + bih (both dirs) ----------------
__global__ __launch_bounds__(256) void xproj_kernel(
    const float* __restrict__ uf,
    const float* __restrict__ Wf_, const float* __restrict__ bf_,
    const float* __restrict__ Wb_, const float* __restrict__ bb_)
{
    __shared__ __align__(16) float As[16][132];
    __shared__ __align__(16) float Ws[16][132];
    const int tid = threadIdx.x;
    const int tx = tid & 15, ty = tid >> 4;
    const int Mbase = blockIdx.x * 128;
    const int Nbase = blockIdx.y * 128;
    const int dir = blockIdx.z;
    const float* W = dir ? Wb_ : Wf_;
    const float* bias = dir ? bb_ : bf_;

    const float* ap[8];
    const float* wp[8];
#pragma unroll
    for (int p = 0; p < 8; p++) {
        int i = tid + p * 256;
        int m = i >> 4, k = i & 15;
        int mg = Mbase + m;
        int tt = mg >> 6, b = mg & 63;
        int srow = dir ? (SS - 1 - tt) : tt;
        ap[p] = uf + ((size_t)b * SS + srow) * DD + k;
        wp[p] = W + (size_t)(Nbase + m) * DD + k;
    }

    ull acc[8][4];
#pragma unroll
    for (int i = 0; i < 8; i++)
#pragma unroll
        for (int j = 0; j < 4; j++) acc[i][j] = 0ull;

    float va[8], vw[8];
#pragma unroll
    for (int p = 0; p < 8; p++) { va[p] = ap[p][0]; vw[p] = wp[p][0]; }

    for (int kt = 0; kt < DD; kt += 16) {
        __syncthreads();
#pragma unroll
        for (int p = 0; p < 8; p++) {
            int i = tid + p * 256;
            As[i & 15][i >> 4] = va[p];
            Ws[i & 15][i >> 4] = vw[p];
        }
        __syncthreads();
        if (kt + 16 < DD) {
#pragma unroll
            for (int p = 0; p < 8; p++) {
                va[p] = ap[p][kt + 16];
                vw[p] = wp[p][kt + 16];
            }
        }
#pragma unroll
        for (int kk = 0; kk < 16; kk++) {
            float4 alo = *(const float4*)&As[kk][ty * 8];
            float4 ahi = *(const float4*)&As[kk][ty * 8 + 4];
            ull a2[8];
            a2[0] = dup2(alo.x); a2[1] = dup2(alo.y);
            a2[2] = dup2(alo.z); a2[3] = dup2(alo.w);
            a2[4] = dup2(ahi.x); a2[5] = dup2(ahi.y);
            a2[6] = dup2(ahi.z); a2[7] = dup2(ahi.w);
            ull b2[4];
#pragma unroll
            for (int jp = 0; jp < 4; jp++)
                b2[jp] = *(const ull*)&Ws[kk][2 * tx + 32 * jp];
#pragma unroll
            for (int i = 0; i < 8; i++)
#pragma unroll
                for (int jp = 0; jp < 4; jp++)
                    FMA2(acc[i][jp], a2[i], b2[jp]);
        }
    }

#pragma unroll
    for (int i = 0; i < 8; i++) {
        int mg = Mbase + ty * 8 + i;
        size_t rowb = ((size_t)dir * SS * BB + mg) * G3;
#pragma unroll
        for (int jp = 0; jp < 4; jp++) {
            int col = Nbase + 2 * tx + 32 * jp;
            F2U u; u.u = acc[i][jp];
            u.f.x += bias[col];
            u.f.y += bias[col + 1];
            *(float2*)&g_xproj[rowb + col] = u.f;
        }
    }
}

// ---------------- big GEMM: g_gcur = [cur,spk,pos] part of all gate projections + bias ----------------
// M = 512*64 (t,b), N = 4096 (4 gates x 1024), K = 1056 (1024 mem + 16 spk + 16 pos)
__global__ __launch_bounds__(256) void gcur_kernel(
    const float* __restrict__ spk, const float* __restrict__ pos,
    const float* __restrict__ Wf, const float* __restrict__ bf,
    const float* __restrict__ Wi, const float* __restrict__ bi,
    const float* __restrict__ Wo, const float* __restrict__ bo,
    const float* __restrict__ Wc, const float* __restrict__ bc)
{
    __shared__ __align__(16) float As[16][132];
    __shared__ __align__(16) float Ws[16][132];
    const int tid = threadIdx.x;
    const int tx = tid & 15, ty = tid >> 4;
    const int Mbase = blockIdx.x * 128;
    const int Nbase = blockIdx.y * 128;
    const int gate = Nbase >> 10;
    const float* W = (gate == 0) ? Wf : (gate == 1) ? Wi : (gate == 2) ? Wo : Wc;
    const float* bias = (gate == 0) ? bf : (gate == 1) ? bi : (gate == 2) ? bo : bc;
    const int wrow = Nbase & 1023;
    const int KTOT = 1056;

    ull acc[8][4];
#pragma unroll
    for (int i = 0; i < 8; i++)
#pragma unroll
        for (int j = 0; j < 4; j++) acc[i][j] = 0ull;

    float va[8], vw[8];
#pragma unroll
    for (int p = 0; p < 8; p++) {
        int i = tid + p * 256;
        int m = i >> 4, kg = i & 15;
        int mg = Mbase + m, t = mg >> 6, b = mg & 63;
        va[p] = g_mem[((size_t)t * BB + b) * HH + kg];     // kg < 16 < 1024
        vw[p] = W[(size_t)(wrow + m) * GINK + kg];
    }

    for (int kt = 0; kt < KTOT; kt += 16) {
        __syncthreads();
#pragma unroll
        for (int p = 0; p < 8; p++) {
            int i = tid + p * 256;
            As[i & 15][i >> 4] = va[p];
            Ws[i & 15][i >> 4] = vw[p];
        }
        __syncthreads();
        if (kt + 16 < KTOT) {
#pragma unroll
            for (int p = 0; p < 8; p++) {
                int i = tid + p * 256;
                int m = i >> 4, kg = kt + 16 + (i & 15);
                int mg = Mbase + m, t = mg >> 6, b = mg & 63;
                float v, wv;
                if (kg < 1024) {
                    v = g_mem[((size_t)t * BB + b) * HH + kg];
                    wv = W[(size_t)(wrow + m) * GINK + kg];
                } else if (kg < 1040) {
                    v = spk[((size_t)b * SS + t) * SPKD + (kg - 1024)];
                    wv = W[(size_t)(wrow + m) * GINK + 2048 + (kg - 1024)];
                } else {
                    v = pos[((size_t)b * SS + t) * SPKD + (kg - 1040)];
                    wv = W[(size_t)(wrow + m) * GINK + 2064 + (kg - 1040)];
                }
                va[p] = v;
                vw[p] = wv;
            }
        }
#pragma unroll
        for (int kk = 0; kk < 16; kk++) {
            float4 alo = *(const float4*)&As[kk][ty * 8];
            float4 ahi = *(const float4*)&As[kk][ty * 8 + 4];
            ull a2[8];
            a2[0] = dup2(alo.x); a2[1] = dup2(alo.y);
            a2[2] = dup2(alo.z); a2[3] = dup2(alo.w);
            a2[4] = dup2(ahi.x); a2[5] = dup2(ahi.y);
            a2[6] = dup2(ahi.z); a2[7] = dup2(ahi.w);
            ull b2[4];
#pragma unroll
            for (int jp = 0; jp < 4; jp++)
                b2[jp] = *(const ull*)&Ws[kk][2 * tx + 32 * jp];
#pragma unroll
            for (int i = 0; i < 8; i++)
#pragma unroll
                for (int jp = 0; jp < 4; jp++)
                    FMA2(acc[i][jp], a2[i], b2[jp]);
        }
    }

#pragma unroll
    for (int i = 0; i < 8; i++) {
        int mg = Mbase + ty * 8 + i;
#pragma unroll
        for (int jp = 0; jp < 4; jp++) {
            int off = 2 * tx + 32 * jp;
            F2U u; u.u = acc[i][jp];
            u.f.x += bias[wrow + off];
            u.f.y += bias[wrow + off + 1];
            *(float2*)&g_gcur[(size_t)mg * 4096 + Nbase + off] = u.f;
        }
    }
}

// ---------------- persistent GRU: 512 steps, 2 grid syncs per step ----------------
__global__ __launch_bounds__(NTHR, 1) void gru_persistent(
    const float* __restrict__ Whh_f, const float* __restrict__ Whh_b,
    const float* __restrict__ bhh_f, const float* __restrict__ bhh_b)
{
    __shared__ __align__(16) float As[16][68];
    __shared__ __align__(16) float Ws[16][260];
    const int tid = threadIdx.x;
    const int tx = tid & 31, ty = tid >> 5;
    const int bx = blockIdx.x;
    unsigned int ls = *(volatile unsigned int*)&g_sense;

    const int w = bx;
    const bool active = (w < 2 * 6 * KS_GRU);
    const int dir = w / (6 * KS_GRU);
    const int rem = w % (6 * KS_GRU);
    const int nt = rem / KS_GRU;
    const int ks = rem % KS_GRU;
    const float* W = dir ? Whh_b : Whh_f;
    const int Nbase = nt * 256;
    const int k0 = ks * 48;
    const int k1 = (k0 + 48 < HH2) ? (k0 + 48) : HH2;

    for (int t = 0; t < SS; t++) {
        if (active) {
            ull acc[8][4];
#pragma unroll
            for (int i = 0; i < 8; i++)
#pragma unroll
                for (int j = 0; j < 4; j++) acc[i][j] = 0ull;

            float va[4], vw[16];
#pragma unroll
            for (int p = 0; p < 4; p++) {
                int i = tid + p * 256;
                int m = i >> 4, kg = k0 + (i & 15);
                float v = 0.f;
                if (t > 0)
                    v = dir ? g_mem[((size_t)(SS - t) * BB + m) * HH + HH2 + kg]
                            : g_mem[((size_t)(t - 1) * BB + m) * HH + kg];
                va[p] = v;
            }
#pragma unroll
            for (int p = 0; p < 16; p++) {
                int i = tid + p * 256;
                int n = i >> 4, kg = k0 + (i & 15);
                vw[p] = W[(size_t)(Nbase + n) * HH2 + kg];
            }

            for (int kt = k0; kt < k1; kt += 16) {
                __syncthreads();
#pragma unroll
                for (int p = 0; p < 4; p++) {
                    int i = tid + p * 256;
                    As[i & 15][i >> 4] = va[p];
                }
#pragma unroll
                for (int p = 0; p < 16; p++) {
                    int i = tid + p * 256;
                    Ws[i & 15][i >> 4] = vw[p];
                }
                __syncthreads();
                if (kt + 16 < k1) {
#pragma unroll
                    for (int p = 0; p < 4; p++) {
                        int i = tid + p * 256;
                        int m = i >> 4, kg = kt + 16 + (i & 15);
                        float v = 0.f;
                        if (t > 0)
                            v = dir ? g_mem[((size_t)(SS - t) * BB + m) * HH + HH2 + kg]
                                    : g_mem[((size_t)(t - 1) * BB + m) * HH + kg];
                        va[p] = v;
                    }
#pragma unroll
                    for (int p = 0; p < 16; p++) {
                        int i = tid + p * 256;
                        int n = i >> 4, kg = kt + 16 + (i & 15);
                        vw[p] = W[(size_t)(Nbase + n) * HH2 + kg];
                    }
                }
                mk64(acc, As, Ws, tx, ty);
            }
#pragma unroll
            for (int i2 = 0; i2 < 8; i2++) {
                int m = ty * 8 + i2;
                size_t rowb = (((size_t)ks * 2 + dir) * BB + m) * G3;
#pragma unroll
                for (int jp = 0; jp < 4; jp++) {
                    int col = Nbase + 2 * tx + 64 * jp;
                    F2U u; u.u = acc[i2][jp];
                    *(float2*)&g_ghp[rowb + col] = u.f;
                }
            }
        }
        gsync(ls);

        for (int e = bx * NTHR + tid; e < 2 * BB * HH2; e += NBLK * NTHR) {
            int d2 = e >> 15;
            int b = (e >> 9) & 63;
            int i = e & 511;
            const float* bhh = d2 ? bhh_b : bhh_f;
            float hr = bhh[i], hz = bhh[HH2 + i], hn = bhh[2 * HH2 + i];
#pragma unroll
            for (int q = 0; q < KS_GRU; q++) {
                size_t base = (((size_t)q * 2 + d2) * BB + b) * G3;
                hr += g_ghp[base + i];
                hz += g_ghp[base + HH2 + i];
                hn += g_ghp[base + 2 * HH2 + i];
            }
            size_t xb = (((size_t)d2 * SS + t) * BB + b) * G3;
            float xr = g_xproj[xb + i], xz = g_xproj[xb + HH2 + i], xn = g_xproj[xb + 2 * HH2 + i];
            float hp = 0.f;
            if (t > 0)
                hp = d2 ? g_mem[((size_t)(SS - t) * BB + b) * HH + HH2 + i]
                        : g_mem[((size_t)(t - 1) * BB + b) * HH + i];
            float r = sigm(xr + hr);
            float z = sigm(xz + hz);
            float n2 = tanhf(xn + r * hn);
            float h = (1.f - z) * n2 + z * hp;
            if (d2 == 0) g_mem[((size_t)t * BB + b) * HH + i] = h;
            else         g_mem[((size_t)(SS - 1 - t) * BB + b) * HH + HH2 + i] = h;
        }
        gsync(ls);
    }
}

// ---------------- seq gate GEMM: A = prev (out[t-1]), N=4096 (16 tiles), K=1024 (8 chunks of 128) ----------------
__device__ __forceinline__ void gate_gemm(int t,
    const float* __restrict__ Wf, const float* __restrict__ Wi,
    const float* __restrict__ Wo, const float* __restrict__ Wc,
    const float* __restrict__ outp,
    float (*As)[68], float (*Ws)[260], int tx, int ty)
{
    const int tid = threadIdx.x;
    const int w = blockIdx.x;
    if (w >= 16 * KS_GATE) return;
    const int nt = w >> 3;
    const int ks = w & 7;
    const int Nbase = nt * 256;
    const int gate = Nbase >> 10;
    const float* W = (gate == 0) ? Wf : (gate == 1) ? Wi : (gate == 2) ? Wo : Wc;
    const int wrow = Nbase & 1023;
    const int k0 = ks * 128;
    const float* prow = outp + ((size_t)(t - 1)) * HH;   // + m*SS*HH

    ull acc[8][4];
#pragma unroll
    for (int i = 0; i < 8; i++)
#pragma unroll
        for (int j = 0; j < 4; j++) acc[i][j] = 0ull;

    float va[4], vw[16];
#pragma unroll
    for (int p = 0; p < 4; p++) {
        int i = tid + p * 256;
        int m = i >> 4, kg = k0 + (i & 15);
        va[p] = prow[(size_t)m * SS * HH + kg];
    }
#pragma unroll
    for (int p = 0; p < 16; p++) {
        int i = tid + p * 256;
        int n = i >> 4, kg = k0 + (i & 15);
        vw[p] = W[(size_t)(wrow + n) * GINK + 1024 + kg];
    }

    for (int kt = k0; kt < k0 + 128; kt += 16) {
        __syncthreads();
#pragma unroll
        for (int p = 0; p < 4; p++) {
            int i = tid + p * 256;
            As[i & 15][i >> 4] = va[p];
        }
#pragma unroll
        for (int p = 0; p < 16; p++) {
            int i = tid + p * 256;
            Ws[i & 15][i >> 4] = vw[p];
        }
        __syncthreads();
        if (kt + 16 < k0 + 128) {
#pragma unroll
            for (int p = 0; p < 4; p++) {
                int i = tid + p * 256;
                int m = i >> 4, kg = kt + 16 + (i & 15);
                va[p] = prow[(size_t)m * SS * HH + kg];
            }
#pragma unroll
            for (int p = 0; p < 16; p++) {
                int i = tid + p * 256;
                int n = i >> 4, kg = kt + 16 + (i & 15);
                vw[p] = W[(size_t)(wrow + n) * GINK + 1024 + kg];
            }
        }
        mk64(acc, (const float (*)[68])As, (const float (*)[260])Ws, tx, ty);
    }
#pragma unroll
    for (int i2 = 0; i2 < 8; i2++) {
        int m = ty * 8 + i2;
        size_t rowb = ((size_t)ks * BB + m) * 4096;
#pragma unroll
        for (int jp = 0; jp < 4; jp++) {
            int col = Nbase + 2 * tx + 64 * jp;
            F2U u; u.u = acc[i2][jp];
            *(float2*)&g_gpre[rowb + col] = u.f;
        }
    }
}

// ---------------- emo1 with fused gate-combine in A-prep ----------------
// N=1024 (4 tiles of 256), K=1024 (32 chunks of 32). Computes its own 64x32 'gated' chunk.
__device__ __forceinline__ void emo1_fused(int t, const float* __restrict__ W1e,
                                           const float* __restrict__ outp,
                                           float (*Gs)[68], float (*Ws)[260],
                                           int tx, int ty)
{
    const int tid = threadIdx.x;
    const int w = blockIdx.x;
    if (w >= 4 * KS_EMO) return;
    const int nt = w >> 5;
    const int ks = w & 31;
    const int Nbase = nt * 256;
    const int k0 = ks * 32;

    // ---- A-prep: compute gated[m][k0..k0+32) into Gs ----
#pragma unroll
    for (int p = 0; p < 8; p++) {
        int e = tid + p * 256;       // 0..2047
        int m = e >> 5, kl = e & 31;
        int i = k0 + kl;
        float gv;
        if (t == 0) {
            gv = g_mem[(size_t)m * HH + i];
        } else {
            const float* gc = &g_gcur[((size_t)t * BB + m) * 4096];
            float f = gc[i], ig = gc[1024 + i], o = gc[2048 + i], c = gc[3072 + i];
#pragma unroll
            for (int q = 0; q < KS_GATE; q++) {
                const float* gp = &g_gpre[((size_t)q * BB + m) * 4096];
                f += gp[i]; ig += gp[1024 + i]; o += gp[2048 + i]; c += gp[3072 + i];
            }
            float prev = outp[((size_t)m * SS + (t - 1)) * HH + i];
            f = sigm(f); ig = sigm(ig); o = sigm(o); c = tanhf(c);
            gv = o * tanhf(f * prev + ig * c);
            if (nt == 0) g_gated[(size_t)m * HH + i] = gv;
        }
        Gs[kl][m] = gv;
    }

    ull acc[8][4];
#pragma unroll
    for (int i = 0; i < 8; i++)
#pragma unroll
        for (int j = 0; j < 4; j++) acc[i][j] = 0ull;

    float vw[16];
#pragma unroll
    for (int p = 0; p < 16; p++) {
        int i = tid + p * 256;
        int n = i >> 4, kg = k0 + (i & 15);
        vw[p] = W1e[(size_t)(Nbase + n) * HH + kg];
    }

#pragma unroll
    for (int kt2 = 0; kt2 < 2; kt2++) {
        __syncthreads();
#pragma unroll
        for (int p = 0; p < 16; p++) {
            int i = tid + p * 256;
            Ws[i & 15][i >> 4] = vw[p];
        }
        __syncthreads();
        if (kt2 == 0) {
#pragma unroll
            for (int p = 0; p < 16; p++) {
                int i = tid + p * 256;
                int n = i >> 4, kg = k0 + 16 + (i & 15);
                vw[p] = W1e[(size_t)(Nbase + n) * HH + kg];
            }
        }
        mk64(acc, (const float (*)[68])(Gs + kt2 * 16), (const float (*)[260])Ws, tx, ty);
    }
#pragma unroll
    for (int i2 = 0; i2 < 8; i2++) {
        int m = ty * 8 + i2;
        size_t rowb = ((size_t)ks * BB + m) * HH;
#pragma unroll
        for (int jp = 0; jp < 4; jp++) {
            int col = Nbase + 2 * tx + 64 * jp;
            F2U u; u.u = acc[i2][jp];
            *(float2*)&g_h1p[rowb + col] = u.f;
        }
    }
}

// ---------------- emo2: A = hln, same shape as emo1 ----------------
__device__ __forceinline__ void emo2_gemm(const float* __restrict__ W2e,
                                          float (*As)[68], float (*Ws)[260],
                                          int tx, int ty)
{
    const int tid = threadIdx.x;
    const int w = blockIdx.x;
    if (w >= 4 * KS_EMO) return;
    const int nt = w >> 5;
    const int ks = w & 31;
    const int Nbase = nt * 256;
    const int k0 = ks * 32;

    ull acc[8][4];
#pragma unroll
    for (int i = 0; i < 8; i++)
#pragma unroll
        for (int j = 0; j < 4; j++) acc[i][j] = 0ull;

    float va[4], vw[16];
#pragma unroll
    for (int p = 0; p < 4; p++) {
        int i = tid + p * 256;
        int m = i >> 4, kg = k0 + (i & 15);
        va[p] = g_hln[(size_t)m * HH + kg];
    }
#pragma unroll
    for (int p = 0; p < 16; p++) {
        int i = tid + p * 256;
        int n = i >> 4, kg = k0 + (i & 15);
        vw[p] = W2e[(size_t)(Nbase + n) * HH + kg];
    }

#pragma unroll
    for (int kt2 = 0; kt2 < 2; kt2++) {
        __syncthreads();
#pragma unroll
        for (int p = 0; p < 4; p++) {
            int i = tid + p * 256;
            As[i & 15][i >> 4] = va[p];
        }
#pragma unroll
        for (int p = 0; p < 16; p++) {
            int i = tid + p * 256;
            Ws[i & 15][i >> 4] = vw[p];
        }
        __syncthreads();
        if (kt2 == 0) {
#pragma unroll
            for (int p = 0; p < 4; p++) {
                int i = tid + p * 256;
                int m = i >> 4, kg = k0 + 16 + (i & 15);
                va[p] = g_hln[(size_t)m * HH + kg];
            }
#pragma unroll
            for (int p = 0; p < 16; p++) {
                int i = tid + p * 256;
                int n = i >> 4, kg = k0 + 16 + (i & 15);
                vw[p] = W2e[(size_t)(Nbase + n) * HH + kg];
            }
        }
        mk64(acc, (const float (*)[68])As, (const float (*)[260])Ws, tx, ty);
    }
#pragma unroll
    for (int i2 = 0; i2 < 8; i2++) {
        int m = ty * 8 + i2;
        size_t rowb = ((size_t)ks * BB + m) * HH;
#pragma unroll
        for (int jp = 0; jp < 4; jp++) {
            int col = Nbase + 2 * tx + 64 * jp;
            F2U u; u.u = acc[i2][jp];
            *(float2*)&g_o2p[rowb + col] = u.f;
        }
    }
}

// ---------------- persistent gating kernel: 512 steps ----------------
__global__ __launch_bounds__(NTHR, 1) void gating_persistent(
    const float* __restrict__ Wfw, const float* __restrict__ Wiw,
    const float* __restrict__ Wow, const float* __restrict__ Wcw,
    const float* __restrict__ W1e, const float* __restrict__ b1e,
    const float* __restrict__ gln, const float* __restrict__ beta,
    const float* __restrict__ W2e, const float* __restrict__ b2e,
    float* __restrict__ out)
{
    __shared__ __align__(16) float As[16][68];
    __shared__ __align__(16) float Ws[16][260];
    __shared__ __align__(16) float Gs[32][68];
    __shared__ float sred[NTHR];
    __shared__ float stats[2];
    const int tid = threadIdx.x;
    const int tx = tid & 31, ty = tid >> 5;
    const int bx = blockIdx.x;
    unsigned int ls = *(volatile unsigned int*)&g_sense;

    for (int t = 0; t < SS; t++) {
        if (t > 0) {
            gate_gemm(t, Wfw, Wiw, Wow, Wcw, out, As, Ws, tx, ty);
            gsync(ls);
        }

        // emo GEMM1 with fused gate-combine
        emo1_fused(t, W1e, out, Gs, Ws, tx, ty);
        gsync(ls);

        // LayerNorm + ReLU (blocks 0..63)
        if (bx < BB) {
            const int b = bx;
            float v[4];
            float lsum = 0.f, lsq = 0.f;
#pragma unroll
            for (int j = 0; j < 4; j++) {
                int i = tid + j * NTHR;
                float x = b1e[i];
#pragma unroll
                for (int q = 0; q < KS_EMO; q++) x += g_h1p[((size_t)q * BB + b) * HH + i];
                v[j] = x; lsum += x; lsq += x * x;
            }
            sred[tid] = lsum; __syncthreads();
            for (int s2 = NTHR / 2; s2 > 0; s2 >>= 1) {
                if (tid < s2) sred[tid] += sred[tid + s2];
                __syncthreads();
            }
            if (tid == 0) stats[0] = sred[0] * (1.f / 1024.f);
            __syncthreads();
            sred[tid] = lsq; __syncthreads();
            for (int s2 = NTHR / 2; s2 > 0; s2 >>= 1) {
                if (tid < s2) sred[tid] += sred[tid + s2];
                __syncthreads();
            }
            if (tid == 0) stats[1] = sred[0] * (1.f / 1024.f);
            __syncthreads();
            float mu = stats[0];
            float var = stats[1] - mu * mu;
            float rs = rsqrtf(var + 1e-5f);
#pragma unroll
            for (int j = 0; j < 4; j++) {
                int i = tid + j * NTHR;
                float y = (v[j] - mu) * rs * gln[i] + beta[i];
                g_hln[(size_t)b * HH + i] = y > 0.f ? y : 0.f;
            }
        }
        gsync(ls);

        // emo GEMM2
        emo2_gemm(W2e, As, Ws, tx, ty);
        gsync(ls);

        // finalize out[t]
        for (int e = bx * NTHR + tid; e < BB * HH; e += NBLK * NTHR) {
            int b = e >> 10, i = e & 1023;
            float x = b2e[i];
#pragma unroll
            for (int q = 0; q < KS_EMO; q++) x += g_o2p[((size_t)q * BB + b) * HH + i];
            float res = (t == 0) ? g_mem[(size_t)b * HH + i] : g_gated[e];
            out[((size_t)b * SS + t) * HH + i] = x + res;
        }
        gsync(ls);
    }
}

// ---------------- host launcher: 4 graph nodes total ----------------
extern "C" void kernel_launch(void* const* d_in, const int* in_sizes, int n_in,
                              void* d_out, int out_size)
{
    (void)in_sizes; (void)n_in; (void)out_size;
    const float* uf    = (const float*)d_in[0];
    const float* spk   = (const float*)d_in[1];
    const float* pos   = (const float*)d_in[2];
    const float* Wih_f = (const float*)d_in[3];
    const float* Whh_f = (const float*)d_in[4];
    const float* bih_f = (const float*)d_in[5];
    const float* bhh_f = (const float*)d_in[6];
    const float* Wih_b = (const float*)d_in[7];
    const float* Whh_b = (const float*)d_in[8];
    const float* bih_b = (const float*)d_in[9];
    const float* bhh_b = (const float*)d_in[10];
    const float* Wfw   = (const float*)d_in[11];
    const float* bfb   = (const float*)d_in[12];
    const float* Wiw   = (const float*)d_in[13];
    const float* bib   = (const float*)d_in[14];
    const float* Wow   = (const float*)d_in[15];
    const float* bob   = (const float*)d_in[16];
    const float* Wcw   = (const float*)d_in[17];
    const float* bcb   = (const float*)d_in[18];
    const float* W1e   = (const float*)d_in[19];
    const float* b1e   = (const float*)d_in[20];
    const float* g_ln  = (const float*)d_in[21];
    const float* beta  = (const float*)d_in[22];
    const float* W2e   = (const float*)d_in[23];
    const float* b2e   = (const float*)d_in[24];
    float* out = (float*)d_out;

    // 1) x projections for both GRU directions
    xproj_kernel<<<dim3(256, 12, 2), 256>>>(uf, Wih_f, bih_f, Wih_b, bih_b);

    // 2) persistent bidirectional GRU recurrence
    gru_persistent<<<NBLK, NTHR>>>(Whh_f, Whh_b, bhh_f, bhh_b);

    // 3) precompute cur/spk/pos part of gate projections (parallel)
    gcur_kernel<<<dim3(256, 32), 256>>>(spk, pos, Wfw, bfb, Wiw, bib,
                                        Wow, bob, Wcw, bcb);

    // 4) persistent dialogue gating loop
    gating_persistent<<<NBLK, NTHR>>>(Wfw, Wiw, Wow, Wcw,
                                      W1e, b1e, g_ln, beta, W2e, b2e, out);
}